// round 15
// baseline (speedup 1.0000x reference)
#include <cuda_runtime.h>
#include <cuda_fp16.h>
#include <math.h>
#include <stdint.h>

// Problem dims (fixed)
#define TB    16
#define LL    1024
#define TT    (TB*LL)     // 16384
#define CLAT  16
#define CC    512
#define NHH   8
#define HDD   64
#define NBLK  4
#define CFF   (4*CC)      // 2048
#define OUTC  8

#define SCALE_L2E 0.1803368801111204f   // 0.125 * log2(e)

// -------------------- scratch (device globals, no allocation) --------------------
__device__ float  g_h    [TT*CC];       // residual stream (fp32)
__device__ __half g_ah   [TT*CC];       // LN out (fp16, GEMM A operand)
__device__ __half g_qkvh [TT*3*CC];     // qkv (fp16; q pre-scaled by SCALE_L2E)
__device__ __half g_attnh[TT*CC];       // attention out (fp16)
__device__ __half g_ffnh [TT*CFF];      // fc1 out (fp16)
__device__ float  g_pool [TB*2*CC];
__device__ float  g_psum [TB*8*CC];     // pool partial sums
__device__ float  g_pmax [TB*8*CC];     // pool partial maxes
__device__ float2 g_lnst [TT];          // final-LN stats (mean, inv) per token
// transposed fp16 weights per block: qkvT(1536x512) oT(512x512) fc1T(2048x512) fc2T(512x2048)
#define WT_QKV_OFF 0
#define WT_O_OFF   786432
#define WT_FC1_OFF 1048576
#define WT_FC2_OFF 2097152
#define WT_BLK     3145728
__device__ __half g_wth [NBLK * WT_BLK];

__device__ __forceinline__ float tanh_fast(float x) {
    float y; asm("tanh.approx.f32 %0, %1;" : "=f"(y) : "f"(x)); return y;
}
__device__ __forceinline__ float gelu_tanh(float x) {
    float x3 = x * x * x;
    return 0.5f * x * (1.0f + tanh_fast(0.7978845608028654f * (x + 0.044715f * x3)));
}

// ==================== PTX helpers (base ISA only) ====================
__device__ __forceinline__ uint32_t smem_u32(const void* p) {
    return (uint32_t)__cvta_generic_to_shared(p);
}
__device__ __forceinline__ void cp_async16(uint32_t saddr, const void* gptr) {
    asm volatile("cp.async.cg.shared.global [%0], [%1], 16;" :: "r"(saddr), "l"(gptr));
}
__device__ __forceinline__ void cp_commit() { asm volatile("cp.async.commit_group;"); }
template<int N> __device__ __forceinline__ void cp_wait() {
    asm volatile("cp.async.wait_group %0;" :: "n"(N));
}
__device__ __forceinline__ void ldsm_x4(uint32_t* r, uint32_t addr) {
    asm volatile("ldmatrix.sync.aligned.m8n8.x4.shared.b16 {%0,%1,%2,%3}, [%4];"
        : "=r"(r[0]), "=r"(r[1]), "=r"(r[2]), "=r"(r[3]) : "r"(addr));
}
__device__ __forceinline__ void ldsm_x4_t(uint32_t* r, uint32_t addr) {
    asm volatile("ldmatrix.sync.aligned.m8n8.x4.trans.shared.b16 {%0,%1,%2,%3}, [%4];"
        : "=r"(r[0]), "=r"(r[1]), "=r"(r[2]), "=r"(r[3]) : "r"(addr));
}
__device__ __forceinline__ void mma_f16(float* d, const uint32_t* a, const uint32_t* b) {
    asm volatile(
        "mma.sync.aligned.m16n8k16.row.col.f32.f16.f16.f32 "
        "{%0,%1,%2,%3}, {%4,%5,%6,%7}, {%8,%9}, {%0,%1,%2,%3};"
        : "+f"(d[0]), "+f"(d[1]), "+f"(d[2]), "+f"(d[3])
        : "r"(a[0]), "r"(a[1]), "r"(a[2]), "r"(a[3]), "r"(b[0]), "r"(b[1]));
}
__device__ __forceinline__ uint32_t packh2(float lo, float hi) {
    __half2 h = __floats2half2_rn(lo, hi);
    return *(uint32_t*)&h;
}

// ==================== fp16 tensor-core GEMM (CTA 128x128, k-chunk 64) =============
// EPI: 0 none, 1 gelu, 2 residual add, 3 qkv (scale cols<512 by SCALE_L2E)
#define GP2   72
#define GST2  18432u
#define GEMM_SMEM (4 * 18432)

template<int EPI, typename OUT>
__global__ __launch_bounds__(256, 2)
void gemm_h_kernel(const __half* __restrict__ A, const __half* __restrict__ Bt,
                   const float* __restrict__ bias, OUT* __restrict__ C,
                   const float* __restrict__ R, int M, int N, int K)
{
    extern __shared__ __half smem_g[];
    const uint32_t base = smem_u32(smem_g);

    const int tid  = threadIdx.x;
    const int lane = tid & 31;
    const int warp = tid >> 5;
    const int warp_m = warp & 1;
    const int warp_n = warp >> 1;
    const int g = lane >> 2;
    const int t = lane & 3;

    const int rowbase = blockIdx.y * 128;
    const int colbase = blockIdx.x * 128;
    const int NK = K >> 6;

    float acc[4][4][4];
    #pragma unroll
    for (int mf = 0; mf < 4; mf++)
        #pragma unroll
        for (int nf = 0; nf < 4; nf++)
            #pragma unroll
            for (int j = 0; j < 4; j++) acc[mf][nf][j] = 0.f;

    auto prefetch = [&](int kt) {
        const uint32_t st = (uint32_t)(kt & 1);
        const uint32_t sa = base + st * GST2;
        const uint32_t sb = base + 2u * GST2 + st * GST2;
        const __half* Ag = A + (size_t)rowbase * K + kt * 64;
        const __half* Bg = Bt + (size_t)colbase * K + kt * 64;
        #pragma unroll
        for (int i = 0; i < 4; i++) {
            int u = tid + i * 256;
            int row = u >> 3, q = u & 7;
            cp_async16(sa + row * (GP2 * 2) + q * 16, Ag + (size_t)row * K + q * 8);
        }
        #pragma unroll
        for (int i = 0; i < 4; i++) {
            int u = tid + i * 256;
            int row = u >> 3, q = u & 7;
            cp_async16(sb + row * (GP2 * 2) + q * 16, Bg + (size_t)row * K + q * 8);
        }
    };

    prefetch(0); cp_commit();

    const uint32_t laneoff = (uint32_t)((lane & 15) * (GP2 * 2) + (lane >> 4) * 16);

    for (int kt = 0; kt < NK; kt++) {
        cp_wait<0>();
        __syncthreads();
        if (kt + 1 < NK) { prefetch(kt + 1); cp_commit(); }

        const uint32_t st = (uint32_t)(kt & 1);
        const uint32_t abase = base + st * GST2 + warp_m * 64 * (GP2 * 2) + laneoff;
        const uint32_t bbase = base + 2u * GST2 + st * GST2 + warp_n * 32 * (GP2 * 2) + laneoff;

        #pragma unroll
        for (int s = 0; s < 4; s++) {
            uint32_t af[4][4];
            #pragma unroll
            for (int mf = 0; mf < 4; mf++)
                ldsm_x4(af[mf], abase + mf * 16 * (GP2 * 2) + s * 32);
            uint32_t bf[4][2];
            #pragma unroll
            for (int nf2 = 0; nf2 < 2; nf2++) {
                uint32_t r[4];
                ldsm_x4(r, bbase + nf2 * 16 * (GP2 * 2) + s * 32);
                bf[2 * nf2 + 0][0] = r[0]; bf[2 * nf2 + 0][1] = r[2];
                bf[2 * nf2 + 1][0] = r[1]; bf[2 * nf2 + 1][1] = r[3];
            }
            #pragma unroll
            for (int mf = 0; mf < 4; mf++)
                #pragma unroll
                for (int nf = 0; nf < 4; nf++)
                    mma_f16(acc[mf][nf], af[mf], bf[nf]);
        }
    }

    #pragma unroll
    for (int mf = 0; mf < 4; mf++) {
        const int r0 = rowbase + warp_m * 64 + mf * 16 + g;
        #pragma unroll
        for (int nf = 0; nf < 4; nf++) {
            const int col = colbase + warp_n * 32 + nf * 8 + t * 2;
            const float b0 = __ldg(bias + col);
            const float b1 = __ldg(bias + col + 1);
            #pragma unroll
            for (int half_i = 0; half_i < 2; half_i++) {
                const int r = r0 + half_i * 8;
                float v0 = acc[mf][nf][half_i * 2 + 0] + b0;
                float v1 = acc[mf][nf][half_i * 2 + 1] + b1;
                const size_t idx = (size_t)r * N + col;
                if (EPI == 1) { v0 = gelu_tanh(v0); v1 = gelu_tanh(v1); }
                else if (EPI == 2) {
                    float2 rr = *(const float2*)(R + idx);
                    v0 += rr.x; v1 += rr.y;
                } else if (EPI == 3) {
                    if (col < 512) { v0 *= SCALE_L2E; v1 *= SCALE_L2E; }  // pre-scale Q
                }
                if (sizeof(OUT) == 2) {
                    __half2 h = __floats2half2_rn(v0, v1);
                    *(__half2*)((__half*)C + idx) = h;
                } else {
                    *(float2*)((float*)C + idx) = make_float2(v0, v1);
                }
            }
        }
    }
}

// ==================== fp16 flash attention (q pre-scaled, Q-prologue hoisted) ======
#define FPAD 72
#define FLASH_SMEM (128*FPAD*2 + 4*64*FPAD*2)   // 55296 B

__global__ __launch_bounds__(256)
void flash_h_kernel(const __half* __restrict__ qkv, __half* __restrict__ o)
{
    extern __shared__ __half smem_f[];
    const uint32_t base = smem_u32(smem_f);
    const int tid  = threadIdx.x;
    const int lane = tid & 31;
    const int w    = tid >> 5;
    const int g    = lane >> 2;
    const int t    = lane & 3;
    const int b = blockIdx.z, h = blockIdx.y, qt = blockIdx.x;

    const size_t tok0 = (size_t)b * LL;

    // Q tile load — its own commit group
    #pragma unroll
    for (int i = 0; i < 4; i++) {
        int u = tid + i * 256;
        int row = u >> 3, q = u & 7;
        cp_async16(base + row * (FPAD * 2) + q * 16,
                   qkv + (tok0 + qt * 128 + row) * 1536 + h * 64 + q * 8);
    }
    cp_commit();

    auto prefetch_kv = [&](int kt) {
        const int buf = kt & 1;
        const uint32_t sk = base + 18432u + buf * 9216u;
        const uint32_t sv = base + 36864u + buf * 9216u;
        #pragma unroll
        for (int i = 0; i < 2; i++) {
            int u = tid + i * 256;
            int row = u >> 3, q = u & 7;
            const __half* src = qkv + (tok0 + kt * 64 + row) * 1536 + h * 64 + q * 8;
            cp_async16(sk + row * (FPAD * 2) + q * 16, src + 512);
            cp_async16(sv + row * (FPAD * 2) + q * 16, src + 1024);
        }
    };
    prefetch_kv(0); cp_commit();

    const uint32_t laneoff = (uint32_t)((lane & 15) * (FPAD * 2) + (lane >> 4) * 16);

    // hoisted Q-fragment load: wait until only the KV0 group is outstanding
    uint32_t aq[4][4];
    cp_wait<1>();
    __syncthreads();
    {
        const uint32_t qb = base + w * 16 * (FPAD * 2) + laneoff;
        #pragma unroll
        for (int s = 0; s < 4; s++) ldsm_x4(aq[s], qb + s * 32);
    }

    float m0 = -INFINITY, m1 = -INFINITY, l0 = 0.f, l1 = 0.f;
    float oacc[8][4];
    #pragma unroll
    for (int nf = 0; nf < 8; nf++)
        #pragma unroll
        for (int j = 0; j < 4; j++) oacc[nf][j] = 0.f;

    for (int kt = 0; kt < 16; kt++) {
        cp_wait<0>();
        __syncthreads();
        if (kt + 1 < 16) { prefetch_kv(kt + 1); cp_commit(); }

        const int buf = kt & 1;
        const uint32_t kb = base + 18432u + buf * 9216u + laneoff;
        const uint32_t vb = base + 36864u + buf * 9216u + laneoff;

        // S = Q @ K^T — scores already in log2 units (q pre-scaled at QKV epilogue)
        float sacc[8][4];
        #pragma unroll
        for (int nf = 0; nf < 8; nf++)
            #pragma unroll
            for (int j = 0; j < 4; j++) sacc[nf][j] = 0.f;
        #pragma unroll
        for (int s = 0; s < 4; s++) {
            #pragma unroll
            for (int j2 = 0; j2 < 4; j2++) {
                uint32_t r[4];
                ldsm_x4(r, kb + j2 * 16 * (FPAD * 2) + s * 32);
                uint32_t bfr0[2] = { r[0], r[2] };
                uint32_t bfr1[2] = { r[1], r[3] };
                mma_f16(sacc[2 * j2 + 0], aq[s], bfr0);
                mma_f16(sacc[2 * j2 + 1], aq[s], bfr1);
            }
        }

        // online softmax (rows g, g+8) in log2 domain — branch-free rescale
        float ml0 = -INFINITY, ml1 = -INFINITY;
        #pragma unroll
        for (int nf = 0; nf < 8; nf++) {
            ml0 = fmaxf(ml0, fmaxf(sacc[nf][0], sacc[nf][1]));
            ml1 = fmaxf(ml1, fmaxf(sacc[nf][2], sacc[nf][3]));
        }
        ml0 = fmaxf(ml0, __shfl_xor_sync(0xffffffffu, ml0, 1));
        ml0 = fmaxf(ml0, __shfl_xor_sync(0xffffffffu, ml0, 2));
        ml1 = fmaxf(ml1, __shfl_xor_sync(0xffffffffu, ml1, 1));
        ml1 = fmaxf(ml1, __shfl_xor_sync(0xffffffffu, ml1, 2));
        const float mn0 = fmaxf(m0, ml0), mn1 = fmaxf(m1, ml1);
        const float c0 = exp2f(m0 - mn0), c1 = exp2f(m1 - mn1);

        float ps0 = 0.f, ps1 = 0.f;
        uint32_t ph0[8], ph1[8];
        #pragma unroll
        for (int nf = 0; nf < 8; nf++) {
            float p0 = exp2f(sacc[nf][0] - mn0);
            float p1 = exp2f(sacc[nf][1] - mn0);
            float p2 = exp2f(sacc[nf][2] - mn1);
            float p3 = exp2f(sacc[nf][3] - mn1);
            ps0 += p0 + p1; ps1 += p2 + p3;
            ph0[nf] = packh2(p0, p1);
            ph1[nf] = packh2(p2, p3);
        }
        ps0 += __shfl_xor_sync(0xffffffffu, ps0, 1);
        ps0 += __shfl_xor_sync(0xffffffffu, ps0, 2);
        ps1 += __shfl_xor_sync(0xffffffffu, ps1, 1);
        ps1 += __shfl_xor_sync(0xffffffffu, ps1, 2);
        l0 = l0 * c0 + ps0; l1 = l1 * c1 + ps1;
        m0 = mn0; m1 = mn1;
        #pragma unroll
        for (int nf = 0; nf < 8; nf++) {
            oacc[nf][0] *= c0; oacc[nf][1] *= c0;
            oacc[nf][2] *= c1; oacc[nf][3] *= c1;
        }

        #pragma unroll
        for (int kk = 0; kk < 4; kk++) {
            uint32_t pa[4] = { ph0[2 * kk], ph1[2 * kk], ph0[2 * kk + 1], ph1[2 * kk + 1] };
            #pragma unroll
            for (int nf2 = 0; nf2 < 4; nf2++) {
                uint32_t r[4];
                ldsm_x4_t(r, vb + kk * 16 * (FPAD * 2) + nf2 * 32);
                uint32_t bfr0[2] = { r[0], r[1] };
                uint32_t bfr1[2] = { r[2], r[3] };
                mma_f16(oacc[2 * nf2 + 0], pa, bfr0);
                mma_f16(oacc[2 * nf2 + 1], pa, bfr1);
            }
        }
    }

    const float i0 = 1.f / l0, i1 = 1.f / l1;
    const size_t row0 = tok0 + qt * 128 + w * 16 + g;
    #pragma unroll
    for (int nf = 0; nf < 8; nf++) {
        const int col = h * 64 + nf * 8 + t * 2;
        __half2 v0 = __floats2half2_rn(oacc[nf][0] * i0, oacc[nf][1] * i0);
        __half2 v1 = __floats2half2_rn(oacc[nf][2] * i1, oacc[nf][3] * i1);
        *(__half2*)(o + row0 * CC + col)       = v0;
        *(__half2*)(o + (row0 + 8) * CC + col) = v1;
    }
}

// -------------------- merged weight transpose (all 4 groups, 1 launch) -----------
__global__ __launch_bounds__(256)
void transpose_all_kernel(const float* __restrict__ Wqkv, const float* __restrict__ Wo,
                          const float* __restrict__ Wfc1, const float* __restrict__ Wfc2,
                          __half* __restrict__ wt)
{
    __shared__ float tbuf[32][33];
    const int bid = blockIdx.x;
    const float* W; __half* Wt; int K, N, tx, ty;
    if (bid < 3072) {
        int b = bid / 768, r = bid % 768;
        K = 512; N = 1536; tx = r % 48; ty = r / 48;
        W = Wqkv + (size_t)b * K * N; Wt = wt + (size_t)b * WT_BLK + WT_QKV_OFF;
    } else if (bid < 4096) {
        int idx = bid - 3072; int b = idx / 256, r = idx % 256;
        K = 512; N = 512; tx = r % 16; ty = r / 16;
        W = Wo + (size_t)b * K * N; Wt = wt + (size_t)b * WT_BLK + WT_O_OFF;
    } else if (bid < 8192) {
        int idx = bid - 4096; int b = idx / 1024, r = idx % 1024;
        K = 512; N = 2048; tx = r % 64; ty = r / 64;
        W = Wfc1 + (size_t)b * K * N; Wt = wt + (size_t)b * WT_BLK + WT_FC1_OFF;
    } else {
        int idx = bid - 8192; int b = idx / 1024, r = idx % 1024;
        K = 2048; N = 512; tx = r % 16; ty = r / 16;
        W = Wfc2 + (size_t)b * K * N; Wt = wt + (size_t)b * WT_BLK + WT_FC2_OFF;
    }
    const int n0 = tx * 32, k0 = ty * 32;
    for (int i = threadIdx.y; i < 32; i += 8)
        tbuf[i][threadIdx.x] = W[(size_t)(k0 + i) * N + n0 + threadIdx.x];
    __syncthreads();
    for (int i = threadIdx.y; i < 32; i += 8)
        Wt[(size_t)(n0 + i) * K + k0 + threadIdx.x] = __float2half_rn(tbuf[threadIdx.x][i]);
}

// -------------------- small SIMT GEMM for input projection (K=16, fp32) ----------
__global__ __launch_bounds__(256)
void gemm_simt_kernel(const float* __restrict__ A, const float* __restrict__ B,
                      const float* __restrict__ bias, float* __restrict__ C,
                      int M, int N, int K)
{
    __shared__ float As[16][128];
    __shared__ float Bs[16][64];
    const int tid = threadIdx.x;
    const int tx = tid & 15, ty = tid >> 4;
    const int row0 = blockIdx.y * 128 + ty * 8;
    const int col0 = blockIdx.x * 64 + tx * 4;

    float acc[8][4];
    #pragma unroll
    for (int i = 0; i < 8; i++)
        #pragma unroll
        for (int j = 0; j < 4; j++) acc[i][j] = 0.f;

    for (int kt = 0; kt < K; kt += 16) {
        for (int i = tid; i < 128 * 16; i += 256) {
            int r = i >> 4, c = i & 15;
            As[c][r] = A[(size_t)(blockIdx.y * 128 + r) * K + kt + c];
        }
        for (int i = tid; i < 16 * 64; i += 256) {
            int r = i >> 6, c = i & 63;
            Bs[r][c] = B[(size_t)(kt + r) * N + blockIdx.x * 64 + c];
        }
        __syncthreads();
        #pragma unroll
        for (int k = 0; k < 16; k++) {
            float a[8], bb[4];
            #pragma unroll
            for (int i = 0; i < 8; i++) a[i] = As[k][ty * 8 + i];
            #pragma unroll
            for (int j = 0; j < 4; j++) bb[j] = Bs[k][tx * 4 + j];
            #pragma unroll
            for (int i = 0; i < 8; i++)
                #pragma unroll
                for (int j = 0; j < 4; j++) acc[i][j] += a[i] * bb[j];
        }
        __syncthreads();
    }
    #pragma unroll
    for (int i = 0; i < 8; i++)
        #pragma unroll
        for (int j = 0; j < 4; j++)
            C[(size_t)(row0 + i) * N + col0 + j] = acc[i][j] + bias[col0 + j];
}

// -------------------- layer norm: warp-per-row, vectorized, no barriers ----------
__global__ __launch_bounds__(256)
void ln_kernel(const float* __restrict__ x, const float* __restrict__ sc,
               const float* __restrict__ bi, __half* __restrict__ y)
{
    const int lane = threadIdx.x & 31;
    const int row  = blockIdx.x * 8 + (threadIdx.x >> 5);
    const float* xr = x + (size_t)row * CC;

    float4 v[4];
    #pragma unroll
    for (int i = 0; i < 4; i++)
        v[i] = *(const float4*)(xr + lane * 4 + i * 128);

    float s = 0.f;
    #pragma unroll
    for (int i = 0; i < 4; i++) s += v[i].x + v[i].y + v[i].z + v[i].w;
    #pragma unroll
    for (int off = 16; off; off >>= 1) s += __shfl_xor_sync(0xffffffffu, s, off);
    const float mean = s * (1.f / 512.f);

    float q = 0.f;
    #pragma unroll
    for (int i = 0; i < 4; i++) {
        v[i].x -= mean; v[i].y -= mean; v[i].z -= mean; v[i].w -= mean;
        q += v[i].x * v[i].x + v[i].y * v[i].y + v[i].z * v[i].z + v[i].w * v[i].w;
    }
    #pragma unroll
    for (int off = 16; off; off >>= 1) q += __shfl_xor_sync(0xffffffffu, q, off);
    const float inv = rsqrtf(q * (1.f / 512.f) + 1e-5f);

    __half* yr = y + (size_t)row * CC;
    #pragma unroll
    for (int i = 0; i < 4; i++) {
        const int c = lane * 4 + i * 128;
        float4 scv = *(const float4*)(sc + c);
        float4 biv = *(const float4*)(bi + c);
        uint2 u;
        u.x = packh2(v[i].x * inv * scv.x + biv.x, v[i].y * inv * scv.y + biv.y);
        u.y = packh2(v[i].z * inv * scv.z + biv.z, v[i].w * inv * scv.w + biv.w);
        *(uint2*)(yr + c) = u;
    }
}

// -------------------- final-LN stats: (mean, inv) per token ----------------------
__global__ __launch_bounds__(256)
void ln_stats_kernel(const float* __restrict__ x, float2* __restrict__ st)
{
    const int lane = threadIdx.x & 31;
    const int row  = blockIdx.x * 8 + (threadIdx.x >> 5);
    const float* xr = x + (size_t)row * CC;

    float4 v[4];
    #pragma unroll
    for (int i = 0; i < 4; i++)
        v[i] = *(const float4*)(xr + lane * 4 + i * 128);

    float s = 0.f;
    #pragma unroll
    for (int i = 0; i < 4; i++) s += v[i].x + v[i].y + v[i].z + v[i].w;
    #pragma unroll
    for (int off = 16; off; off >>= 1) s += __shfl_xor_sync(0xffffffffu, s, off);
    const float mean = s * (1.f / 512.f);

    float q = 0.f;
    #pragma unroll
    for (int i = 0; i < 4; i++) {
        float dx = v[i].x - mean, dy = v[i].y - mean, dz = v[i].z - mean, dw = v[i].w - mean;
        q += dx * dx + dy * dy + dz * dz + dw * dw;
    }
    #pragma unroll
    for (int off = 16; off; off >>= 1) q += __shfl_xor_sync(0xffffffffu, q, off);
    if (lane == 0)
        st[row] = make_float2(mean, rsqrtf(q * (1.f / 512.f) + 1e-5f));
}

// -------------------- segmented mean+max pool (two-phase, LN fused) --------------
__global__ __launch_bounds__(128)
void pool1_kernel(const float* __restrict__ hf, const float2* __restrict__ st,
                  float* __restrict__ psum, float* __restrict__ pmax)
{
    const int b = blockIdx.x;
    const int c = blockIdx.y * 128 + threadIdx.x;
    const int lc = blockIdx.z;
    const int tokbase = b * LL + lc * 128;
    const float* p = hf + (size_t)tokbase * CC + c;
    float s = 0.f, mx = -INFINITY;
    #pragma unroll 4
    for (int l = 0; l < 128; l++) {
        float2 stv = st[tokbase + l];
        float v = (p[(size_t)l * CC] - stv.x) * stv.y;
        s += v;
        mx = fmaxf(mx, v);
    }
    const size_t idx = ((size_t)(b * 8 + lc)) * CC + c;
    psum[idx] = s;
    pmax[idx] = mx;
}
__global__ __launch_bounds__(128)
void pool2_kernel(const float* __restrict__ psum, const float* __restrict__ pmax,
                  float* __restrict__ gp)
{
    const int b = blockIdx.x;
    const int c = blockIdx.y * 128 + threadIdx.x;
    float s = 0.f, mx = -INFINITY;
    #pragma unroll
    for (int lc = 0; lc < 8; lc++) {
        const size_t idx = ((size_t)(b * 8 + lc)) * CC + c;
        s += psum[idx];
        mx = fmaxf(mx, pmax[idx]);
    }
    gp[b * (2 * CC) + c]      = s * (1.f / (float)LL);
    gp[b * (2 * CC) + CC + c] = mx;
}

// -------------------- head ------------------------------------------------------
__global__ __launch_bounds__(128)
void head_kernel(const float* __restrict__ gp, const float* __restrict__ W,
                 const float* __restrict__ bh, float* __restrict__ out)
{
    const int tid = threadIdx.x;
    const int b = tid >> 3, o = tid & 7;
    float acc = bh[o];
    const float* gr = gp + b * 1024;
    for (int k = 0; k < 1024; k++) acc += gr[k] * W[k * 8 + o];
    out[b * 8 + o] = acc;
}

// -------------------- host launch -----------------------------------------------
static void* sym_addr(const void* sym) {
    void* p = nullptr;
    cudaGetSymbolAddress(&p, sym);
    return p;
}

extern "C" void kernel_launch(void* const* d_in, const int* in_sizes, int n_in,
                              void* d_out, int out_size)
{
    const float* feats  = (const float*)d_in[0];
    // d_in[1] = batch_idx (equal segments by construction) — unused
    const float* W_in   = (const float*)d_in[2];
    const float* b_in   = (const float*)d_in[3];
    const float* ln1_s  = (const float*)d_in[4];
    const float* ln1_b  = (const float*)d_in[5];
    const float* W_qkv  = (const float*)d_in[6];
    const float* b_qkv  = (const float*)d_in[7];
    const float* W_o    = (const float*)d_in[8];
    const float* b_o    = (const float*)d_in[9];
    const float* ln2_s  = (const float*)d_in[10];
    const float* ln2_b  = (const float*)d_in[11];
    const float* W_fc1  = (const float*)d_in[12];
    const float* b_fc1  = (const float*)d_in[13];
    const float* W_fc2  = (const float*)d_in[14];
    const float* b_fc2  = (const float*)d_in[15];
    const float* W_head = (const float*)d_in[16];
    const float* b_head = (const float*)d_in[17];
    float* out = (float*)d_out;

    float*  h     = (float*)sym_addr(g_h);
    __half* ah    = (__half*)sym_addr(g_ah);
    __half* qkvh  = (__half*)sym_addr(g_qkvh);
    __half* attnh = (__half*)sym_addr(g_attnh);
    __half* ffnh  = (__half*)sym_addr(g_ffnh);
    float*  pool  = (float*)sym_addr(g_pool);
    float*  psum  = (float*)sym_addr(g_psum);
    float*  pmax  = (float*)sym_addr(g_pmax);
    float2* lnst  = (float2*)sym_addr(g_lnst);
    __half* wt    = (__half*)sym_addr(g_wth);

    cudaFuncSetAttribute(gemm_h_kernel<3, __half>, cudaFuncAttributeMaxDynamicSharedMemorySize, GEMM_SMEM);
    cudaFuncSetAttribute(gemm_h_kernel<1, __half>, cudaFuncAttributeMaxDynamicSharedMemorySize, GEMM_SMEM);
    cudaFuncSetAttribute(gemm_h_kernel<2, float>,  cudaFuncAttributeMaxDynamicSharedMemorySize, GEMM_SMEM);
    cudaFuncSetAttribute(flash_h_kernel, cudaFuncAttributeMaxDynamicSharedMemorySize, FLASH_SMEM);

    // all weight transposes in one launch
    transpose_all_kernel<<<12288, dim3(32, 8)>>>(W_qkv, W_o, W_fc1, W_fc2, wt);

    // input projection: h = feats @ W_in + b_in   [16384,16]x[16,512] (fp32)
    gemm_simt_kernel<<<dim3(CC/64, TT/128), 256>>>(feats, W_in, b_in, h, TT, CC, CLAT);

    for (int i = 0; i < NBLK; i++) {
        __half* wb = wt + (size_t)i * WT_BLK;
        ln_kernel<<<TT/8, 256>>>(h, ln1_s + i * CC, ln1_b + i * CC, ah);
        gemm_h_kernel<3, __half><<<dim3(12, 128), 256, GEMM_SMEM>>>(
            ah, wb + WT_QKV_OFF, b_qkv + i * 3 * CC, qkvh, nullptr, TT, 3 * CC, CC);
        flash_h_kernel<<<dim3(8, NHH, TB), 256, FLASH_SMEM>>>(qkvh, attnh);
        gemm_h_kernel<2, float><<<dim3(4, 128), 256, GEMM_SMEM>>>(
            attnh, wb + WT_O_OFF, b_o + i * CC, h, h, TT, CC, CC);
        ln_kernel<<<TT/8, 256>>>(h, ln2_s + i * CC, ln2_b + i * CC, ah);
        gemm_h_kernel<1, __half><<<dim3(16, 128), 256, GEMM_SMEM>>>(
            ah, wb + WT_FC1_OFF, b_fc1 + i * CFF, ffnh, nullptr, TT, CFF, CC);
        gemm_h_kernel<2, float><<<dim3(4, 128), 256, GEMM_SMEM>>>(
            ffnh, wb + WT_FC2_OFF, b_fc2 + i * CC, h, h, TT, CC, CFF);
    }

    ln_stats_kernel<<<TT/8, 256>>>(h, lnst);
    pool1_kernel<<<dim3(TB, CC / 128, 8), 128>>>(h, lnst, psum, pmax);
    pool2_kernel<<<dim3(TB, CC / 128), 128>>>(psum, pmax, pool);
    head_kernel<<<1, 128>>>(pool, W_head, b_head, out);
    (void)in_sizes; (void)n_in; (void)out_size;
}

// round 16
// speedup vs baseline: 1.0089x; 1.0089x over previous
#include <cuda_runtime.h>
#include <cuda_fp16.h>
#include <math.h>
#include <stdint.h>

// Problem dims (fixed)
#define TB    16
#define LL    1024
#define TT    (TB*LL)     // 16384
#define CLAT  16
#define CC    512
#define NHH   8
#define HDD   64
#define NBLK  4
#define CFF   (4*CC)      // 2048
#define OUTC  8

// -------------------- scratch (device globals, no allocation) --------------------
__device__ float  g_h    [TT*CC];       // residual stream (fp32)
__device__ __half g_ah   [TT*CC];       // LN out (fp16, GEMM A operand)
__device__ __half g_qkvh [TT*3*CC];     // qkv (fp16)
__device__ __half g_attnh[TT*CC];       // attention out (fp16)
__device__ __half g_ffnh [TT*CFF];      // fc1 out (fp16)
__device__ float  g_pool [TB*2*CC];
__device__ float  g_psum [TB*8*CC];     // pool partial sums
__device__ float  g_pmax [TB*8*CC];     // pool partial maxes
__device__ float2 g_lnst [TT];          // final-LN stats (mean, inv) per token
// transposed fp16 weights per block: qkvT(1536x512) oT(512x512) fc1T(2048x512) fc2T(512x2048)
#define WT_QKV_OFF 0
#define WT_O_OFF   786432
#define WT_FC1_OFF 1048576
#define WT_FC2_OFF 2097152
#define WT_BLK     3145728
__device__ __half g_wth [NBLK * WT_BLK];

__device__ __forceinline__ float tanh_fast(float x) {
    float y; asm("tanh.approx.f32 %0, %1;" : "=f"(y) : "f"(x)); return y;
}
__device__ __forceinline__ float gelu_tanh(float x) {
    float x3 = x * x * x;
    return 0.5f * x * (1.0f + tanh_fast(0.7978845608028654f * (x + 0.044715f * x3)));
}

// ==================== PTX helpers (base ISA only) ====================
__device__ __forceinline__ uint32_t smem_u32(const void* p) {
    return (uint32_t)__cvta_generic_to_shared(p);
}
__device__ __forceinline__ void cp_async16(uint32_t saddr, const void* gptr) {
    asm volatile("cp.async.cg.shared.global [%0], [%1], 16;" :: "r"(saddr), "l"(gptr));
}
__device__ __forceinline__ void cp_commit() { asm volatile("cp.async.commit_group;"); }
template<int N> __device__ __forceinline__ void cp_wait() {
    asm volatile("cp.async.wait_group %0;" :: "n"(N));
}
__device__ __forceinline__ void ldsm_x4(uint32_t* r, uint32_t addr) {
    asm volatile("ldmatrix.sync.aligned.m8n8.x4.shared.b16 {%0,%1,%2,%3}, [%4];"
        : "=r"(r[0]), "=r"(r[1]), "=r"(r[2]), "=r"(r[3]) : "r"(addr));
}
__device__ __forceinline__ void ldsm_x4_t(uint32_t* r, uint32_t addr) {
    asm volatile("ldmatrix.sync.aligned.m8n8.x4.trans.shared.b16 {%0,%1,%2,%3}, [%4];"
        : "=r"(r[0]), "=r"(r[1]), "=r"(r[2]), "=r"(r[3]) : "r"(addr));
}
__device__ __forceinline__ void mma_f16(float* d, const uint32_t* a, const uint32_t* b) {
    asm volatile(
        "mma.sync.aligned.m16n8k16.row.col.f32.f16.f16.f32 "
        "{%0,%1,%2,%3}, {%4,%5,%6,%7}, {%8,%9}, {%0,%1,%2,%3};"
        : "+f"(d[0]), "+f"(d[1]), "+f"(d[2]), "+f"(d[3])
        : "r"(a[0]), "r"(a[1]), "r"(a[2]), "r"(a[3]), "r"(b[0]), "r"(b[1]));
}
__device__ __forceinline__ uint32_t packh2(float lo, float hi) {
    __half2 h = __floats2half2_rn(lo, hi);
    return *(uint32_t*)&h;
}

// ==================== fp16 tensor-core GEMM (CTA 128x128, k-chunk 64) =============
// (champion config)
#define GP2   72
#define GST2  18432u
#define GEMM_SMEM (4 * 18432)

template<int EPI, typename OUT>
__global__ __launch_bounds__(256, 2)
void gemm_h_kernel(const __half* __restrict__ A, const __half* __restrict__ Bt,
                   const float* __restrict__ bias, OUT* __restrict__ C,
                   const float* __restrict__ R, int M, int N, int K)
{
    extern __shared__ __half smem_g[];
    const uint32_t base = smem_u32(smem_g);

    const int tid  = threadIdx.x;
    const int lane = tid & 31;
    const int warp = tid >> 5;
    const int warp_m = warp & 1;
    const int warp_n = warp >> 1;
    const int g = lane >> 2;
    const int t = lane & 3;

    const int rowbase = blockIdx.y * 128;
    const int colbase = blockIdx.x * 128;
    const int NK = K >> 6;

    float acc[4][4][4];
    #pragma unroll
    for (int mf = 0; mf < 4; mf++)
        #pragma unroll
        for (int nf = 0; nf < 4; nf++)
            #pragma unroll
            for (int j = 0; j < 4; j++) acc[mf][nf][j] = 0.f;

    auto prefetch = [&](int kt) {
        const uint32_t st = (uint32_t)(kt & 1);
        const uint32_t sa = base + st * GST2;
        const uint32_t sb = base + 2u * GST2 + st * GST2;
        const __half* Ag = A + (size_t)rowbase * K + kt * 64;
        const __half* Bg = Bt + (size_t)colbase * K + kt * 64;
        #pragma unroll
        for (int i = 0; i < 4; i++) {
            int u = tid + i * 256;
            int row = u >> 3, q = u & 7;
            cp_async16(sa + row * (GP2 * 2) + q * 16, Ag + (size_t)row * K + q * 8);
        }
        #pragma unroll
        for (int i = 0; i < 4; i++) {
            int u = tid + i * 256;
            int row = u >> 3, q = u & 7;
            cp_async16(sb + row * (GP2 * 2) + q * 16, Bg + (size_t)row * K + q * 8);
        }
    };

    prefetch(0); cp_commit();

    const uint32_t laneoff = (uint32_t)((lane & 15) * (GP2 * 2) + (lane >> 4) * 16);

    for (int kt = 0; kt < NK; kt++) {
        cp_wait<0>();
        __syncthreads();
        if (kt + 1 < NK) { prefetch(kt + 1); cp_commit(); }

        const uint32_t st = (uint32_t)(kt & 1);
        const uint32_t abase = base + st * GST2 + warp_m * 64 * (GP2 * 2) + laneoff;
        const uint32_t bbase = base + 2u * GST2 + st * GST2 + warp_n * 32 * (GP2 * 2) + laneoff;

        #pragma unroll
        for (int s = 0; s < 4; s++) {
            uint32_t af[4][4];
            #pragma unroll
            for (int mf = 0; mf < 4; mf++)
                ldsm_x4(af[mf], abase + mf * 16 * (GP2 * 2) + s * 32);
            uint32_t bf[4][2];
            #pragma unroll
            for (int nf2 = 0; nf2 < 2; nf2++) {
                uint32_t r[4];
                ldsm_x4(r, bbase + nf2 * 16 * (GP2 * 2) + s * 32);
                bf[2 * nf2 + 0][0] = r[0]; bf[2 * nf2 + 0][1] = r[2];
                bf[2 * nf2 + 1][0] = r[1]; bf[2 * nf2 + 1][1] = r[3];
            }
            #pragma unroll
            for (int mf = 0; mf < 4; mf++)
                #pragma unroll
                for (int nf = 0; nf < 4; nf++)
                    mma_f16(acc[mf][nf], af[mf], bf[nf]);
        }
    }

    #pragma unroll
    for (int mf = 0; mf < 4; mf++) {
        const int r0 = rowbase + warp_m * 64 + mf * 16 + g;
        #pragma unroll
        for (int nf = 0; nf < 4; nf++) {
            const int col = colbase + warp_n * 32 + nf * 8 + t * 2;
            const float b0 = __ldg(bias + col);
            const float b1 = __ldg(bias + col + 1);
            #pragma unroll
            for (int half_i = 0; half_i < 2; half_i++) {
                const int r = r0 + half_i * 8;
                float v0 = acc[mf][nf][half_i * 2 + 0] + b0;
                float v1 = acc[mf][nf][half_i * 2 + 1] + b1;
                const size_t idx = (size_t)r * N + col;
                if (EPI == 1) { v0 = gelu_tanh(v0); v1 = gelu_tanh(v1); }
                else if (EPI == 2) {
                    float2 rr = *(const float2*)(R + idx);
                    v0 += rr.x; v1 += rr.y;
                }
                if (sizeof(OUT) == 2) {
                    __half2 h = __floats2half2_rn(v0, v1);
                    *(__half2*)((__half*)C + idx) = h;
                } else {
                    *(float2*)((float*)C + idx) = make_float2(v0, v1);
                }
            }
        }
    }
}

// ==================== fp16 flash attention (log2 softmax, Q-prologue hoisted) ======
#define FPAD 72
#define FLASH_SMEM (128*FPAD*2 + 4*64*FPAD*2)   // 55296 B
#define SCALE_L2E 0.1803368801111204f           // 0.125 * log2(e)

__global__ __launch_bounds__(256)
void flash_h_kernel(const __half* __restrict__ qkv, __half* __restrict__ o)
{
    extern __shared__ __half smem_f[];
    const uint32_t base = smem_u32(smem_f);
    const int tid  = threadIdx.x;
    const int lane = tid & 31;
    const int w    = tid >> 5;
    const int g    = lane >> 2;
    const int t    = lane & 3;
    const int b = blockIdx.z, h = blockIdx.y, qt = blockIdx.x;

    const size_t tok0 = (size_t)b * LL;

    // Q tile load — its own commit group
    #pragma unroll
    for (int i = 0; i < 4; i++) {
        int u = tid + i * 256;
        int row = u >> 3, q = u & 7;
        cp_async16(base + row * (FPAD * 2) + q * 16,
                   qkv + (tok0 + qt * 128 + row) * 1536 + h * 64 + q * 8);
    }
    cp_commit();

    auto prefetch_kv = [&](int kt) {
        const int buf = kt & 1;
        const uint32_t sk = base + 18432u + buf * 9216u;
        const uint32_t sv = base + 36864u + buf * 9216u;
        #pragma unroll
        for (int i = 0; i < 2; i++) {
            int u = tid + i * 256;
            int row = u >> 3, q = u & 7;
            const __half* src = qkv + (tok0 + kt * 64 + row) * 1536 + h * 64 + q * 8;
            cp_async16(sk + row * (FPAD * 2) + q * 16, src + 512);
            cp_async16(sv + row * (FPAD * 2) + q * 16, src + 1024);
        }
    };
    prefetch_kv(0); cp_commit();

    const uint32_t laneoff = (uint32_t)((lane & 15) * (FPAD * 2) + (lane >> 4) * 16);

    // hoisted Q-fragment load: wait until only the KV0 group is outstanding
    uint32_t aq[4][4];
    cp_wait<1>();
    __syncthreads();
    {
        const uint32_t qb = base + w * 16 * (FPAD * 2) + laneoff;
        #pragma unroll
        for (int s = 0; s < 4; s++) ldsm_x4(aq[s], qb + s * 32);
    }

    float m0 = -INFINITY, m1 = -INFINITY, l0 = 0.f, l1 = 0.f;
    float oacc[8][4];
    #pragma unroll
    for (int nf = 0; nf < 8; nf++)
        #pragma unroll
        for (int j = 0; j < 4; j++) oacc[nf][j] = 0.f;

    for (int kt = 0; kt < 16; kt++) {
        cp_wait<0>();
        __syncthreads();
        if (kt + 1 < 16) { prefetch_kv(kt + 1); cp_commit(); }

        const int buf = kt & 1;
        const uint32_t kb = base + 18432u + buf * 9216u + laneoff;
        const uint32_t vb = base + 36864u + buf * 9216u + laneoff;

        float sacc[8][4];
        #pragma unroll
        for (int nf = 0; nf < 8; nf++)
            #pragma unroll
            for (int j = 0; j < 4; j++) sacc[nf][j] = 0.f;
        #pragma unroll
        for (int s = 0; s < 4; s++) {
            #pragma unroll
            for (int j2 = 0; j2 < 4; j2++) {
                uint32_t r[4];
                ldsm_x4(r, kb + j2 * 16 * (FPAD * 2) + s * 32);
                uint32_t bfr0[2] = { r[0], r[2] };
                uint32_t bfr1[2] = { r[1], r[3] };
                mma_f16(sacc[2 * j2 + 0], aq[s], bfr0);
                mma_f16(sacc[2 * j2 + 1], aq[s], bfr1);
            }
        }

        float ml0 = -INFINITY, ml1 = -INFINITY;
        #pragma unroll
        for (int nf = 0; nf < 8; nf++) {
            #pragma unroll
            for (int j = 0; j < 4; j++) sacc[nf][j] *= SCALE_L2E;
            ml0 = fmaxf(ml0, fmaxf(sacc[nf][0], sacc[nf][1]));
            ml1 = fmaxf(ml1, fmaxf(sacc[nf][2], sacc[nf][3]));
        }
        ml0 = fmaxf(ml0, __shfl_xor_sync(0xffffffffu, ml0, 1));
        ml0 = fmaxf(ml0, __shfl_xor_sync(0xffffffffu, ml0, 2));
        ml1 = fmaxf(ml1, __shfl_xor_sync(0xffffffffu, ml1, 1));
        ml1 = fmaxf(ml1, __shfl_xor_sync(0xffffffffu, ml1, 2));
        const float mn0 = fmaxf(m0, ml0), mn1 = fmaxf(m1, ml1);
        const float c0 = exp2f(m0 - mn0), c1 = exp2f(m1 - mn1);

        float ps0 = 0.f, ps1 = 0.f;
        uint32_t ph0[8], ph1[8];
        #pragma unroll
        for (int nf = 0; nf < 8; nf++) {
            float p0 = exp2f(sacc[nf][0] - mn0);
            float p1 = exp2f(sacc[nf][1] - mn0);
            float p2 = exp2f(sacc[nf][2] - mn1);
            float p3 = exp2f(sacc[nf][3] - mn1);
            ps0 += p0 + p1; ps1 += p2 + p3;
            ph0[nf] = packh2(p0, p1);
            ph1[nf] = packh2(p2, p3);
        }
        ps0 += __shfl_xor_sync(0xffffffffu, ps0, 1);
        ps0 += __shfl_xor_sync(0xffffffffu, ps0, 2);
        ps1 += __shfl_xor_sync(0xffffffffu, ps1, 1);
        ps1 += __shfl_xor_sync(0xffffffffu, ps1, 2);
        l0 = l0 * c0 + ps0; l1 = l1 * c1 + ps1;
        m0 = mn0; m1 = mn1;
        #pragma unroll
        for (int nf = 0; nf < 8; nf++) {
            oacc[nf][0] *= c0; oacc[nf][1] *= c0;
            oacc[nf][2] *= c1; oacc[nf][3] *= c1;
        }

        #pragma unroll
        for (int kk = 0; kk < 4; kk++) {
            uint32_t pa[4] = { ph0[2 * kk], ph1[2 * kk], ph0[2 * kk + 1], ph1[2 * kk + 1] };
            #pragma unroll
            for (int nf2 = 0; nf2 < 4; nf2++) {
                uint32_t r[4];
                ldsm_x4_t(r, vb + kk * 16 * (FPAD * 2) + nf2 * 32);
                uint32_t bfr0[2] = { r[0], r[1] };
                uint32_t bfr1[2] = { r[2], r[3] };
                mma_f16(oacc[2 * nf2 + 0], pa, bfr0);
                mma_f16(oacc[2 * nf2 + 1], pa, bfr1);
            }
        }
    }

    const float i0 = 1.f / l0, i1 = 1.f / l1;
    const size_t row0 = tok0 + qt * 128 + w * 16 + g;
    #pragma unroll
    for (int nf = 0; nf < 8; nf++) {
        const int col = h * 64 + nf * 8 + t * 2;
        __half2 v0 = __floats2half2_rn(oacc[nf][0] * i0, oacc[nf][1] * i0);
        __half2 v1 = __floats2half2_rn(oacc[nf][2] * i1, oacc[nf][3] * i1);
        *(__half2*)(o + row0 * CC + col)       = v0;
        *(__half2*)(o + (row0 + 8) * CC + col) = v1;
    }
}

// -------------------- merged weight transpose (all 4 groups, 1 launch) -----------
__global__ __launch_bounds__(256)
void transpose_all_kernel(const float* __restrict__ Wqkv, const float* __restrict__ Wo,
                          const float* __restrict__ Wfc1, const float* __restrict__ Wfc2,
                          __half* __restrict__ wt)
{
    __shared__ float tbuf[32][33];
    const int bid = blockIdx.x;
    const float* W; __half* Wt; int K, N, tx, ty;
    if (bid < 3072) {
        int b = bid / 768, r = bid % 768;
        K = 512; N = 1536; tx = r % 48; ty = r / 48;
        W = Wqkv + (size_t)b * K * N; Wt = wt + (size_t)b * WT_BLK + WT_QKV_OFF;
    } else if (bid < 4096) {
        int idx = bid - 3072; int b = idx / 256, r = idx % 256;
        K = 512; N = 512; tx = r % 16; ty = r / 16;
        W = Wo + (size_t)b * K * N; Wt = wt + (size_t)b * WT_BLK + WT_O_OFF;
    } else if (bid < 8192) {
        int idx = bid - 4096; int b = idx / 1024, r = idx % 1024;
        K = 512; N = 2048; tx = r % 64; ty = r / 64;
        W = Wfc1 + (size_t)b * K * N; Wt = wt + (size_t)b * WT_BLK + WT_FC1_OFF;
    } else {
        int idx = bid - 8192; int b = idx / 1024, r = idx % 1024;
        K = 2048; N = 512; tx = r % 16; ty = r / 16;
        W = Wfc2 + (size_t)b * K * N; Wt = wt + (size_t)b * WT_BLK + WT_FC2_OFF;
    }
    const int n0 = tx * 32, k0 = ty * 32;
    for (int i = threadIdx.y; i < 32; i += 8)
        tbuf[i][threadIdx.x] = W[(size_t)(k0 + i) * N + n0 + threadIdx.x];
    __syncthreads();
    for (int i = threadIdx.y; i < 32; i += 8)
        Wt[(size_t)(n0 + i) * K + k0 + threadIdx.x] = __float2half_rn(tbuf[threadIdx.x][i]);
}

// -------------------- small SIMT GEMM for input projection (K=16, fp32) ----------
__global__ __launch_bounds__(256)
void gemm_simt_kernel(const float* __restrict__ A, const float* __restrict__ B,
                      const float* __restrict__ bias, float* __restrict__ C,
                      int M, int N, int K)
{
    __shared__ float As[16][128];
    __shared__ float Bs[16][64];
    const int tid = threadIdx.x;
    const int tx = tid & 15, ty = tid >> 4;
    const int row0 = blockIdx.y * 128 + ty * 8;
    const int col0 = blockIdx.x * 64 + tx * 4;

    float acc[8][4];
    #pragma unroll
    for (int i = 0; i < 8; i++)
        #pragma unroll
        for (int j = 0; j < 4; j++) acc[i][j] = 0.f;

    for (int kt = 0; kt < K; kt += 16) {
        for (int i = tid; i < 128 * 16; i += 256) {
            int r = i >> 4, c = i & 15;
            As[c][r] = A[(size_t)(blockIdx.y * 128 + r) * K + kt + c];
        }
        for (int i = tid; i < 16 * 64; i += 256) {
            int r = i >> 6, c = i & 63;
            Bs[r][c] = B[(size_t)(kt + r) * N + blockIdx.x * 64 + c];
        }
        __syncthreads();
        #pragma unroll
        for (int k = 0; k < 16; k++) {
            float a[8], bb[4];
            #pragma unroll
            for (int i = 0; i < 8; i++) a[i] = As[k][ty * 8 + i];
            #pragma unroll
            for (int j = 0; j < 4; j++) bb[j] = Bs[k][tx * 4 + j];
            #pragma unroll
            for (int i = 0; i < 8; i++)
                #pragma unroll
                for (int j = 0; j < 4; j++) acc[i][j] += a[i] * bb[j];
        }
        __syncthreads();
    }
    #pragma unroll
    for (int i = 0; i < 8; i++)
        #pragma unroll
        for (int j = 0; j < 4; j++)
            C[(size_t)(row0 + i) * N + col0 + j] = acc[i][j] + bias[col0 + j];
}

// -------------------- layer norm: warp-per-row, vectorized, no barriers ----------
__global__ __launch_bounds__(256)
void ln_kernel(const float* __restrict__ x, const float* __restrict__ sc,
               const float* __restrict__ bi, __half* __restrict__ y)
{
    const int lane = threadIdx.x & 31;
    const int row  = blockIdx.x * 8 + (threadIdx.x >> 5);
    const float* xr = x + (size_t)row * CC;

    float4 v[4];
    #pragma unroll
    for (int i = 0; i < 4; i++)
        v[i] = *(const float4*)(xr + lane * 4 + i * 128);

    float s = 0.f;
    #pragma unroll
    for (int i = 0; i < 4; i++) s += v[i].x + v[i].y + v[i].z + v[i].w;
    #pragma unroll
    for (int off = 16; off; off >>= 1) s += __shfl_xor_sync(0xffffffffu, s, off);
    const float mean = s * (1.f / 512.f);

    float q = 0.f;
    #pragma unroll
    for (int i = 0; i < 4; i++) {
        v[i].x -= mean; v[i].y -= mean; v[i].z -= mean; v[i].w -= mean;
        q += v[i].x * v[i].x + v[i].y * v[i].y + v[i].z * v[i].z + v[i].w * v[i].w;
    }
    #pragma unroll
    for (int off = 16; off; off >>= 1) q += __shfl_xor_sync(0xffffffffu, q, off);
    const float inv = rsqrtf(q * (1.f / 512.f) + 1e-5f);

    __half* yr = y + (size_t)row * CC;
    #pragma unroll
    for (int i = 0; i < 4; i++) {
        const int c = lane * 4 + i * 128;
        float4 scv = *(const float4*)(sc + c);
        float4 biv = *(const float4*)(bi + c);
        uint2 u;
        u.x = packh2(v[i].x * inv * scv.x + biv.x, v[i].y * inv * scv.y + biv.y);
        u.y = packh2(v[i].z * inv * scv.z + biv.z, v[i].w * inv * scv.w + biv.w);
        *(uint2*)(yr + c) = u;
    }
}

// -------------------- final-LN stats: (mean, inv) per token ----------------------
__global__ __launch_bounds__(256)
void ln_stats_kernel(const float* __restrict__ x, float2* __restrict__ st)
{
    const int lane = threadIdx.x & 31;
    const int row  = blockIdx.x * 8 + (threadIdx.x >> 5);
    const float* xr = x + (size_t)row * CC;

    float4 v[4];
    #pragma unroll
    for (int i = 0; i < 4; i++)
        v[i] = *(const float4*)(xr + lane * 4 + i * 128);

    float s = 0.f;
    #pragma unroll
    for (int i = 0; i < 4; i++) s += v[i].x + v[i].y + v[i].z + v[i].w;
    #pragma unroll
    for (int off = 16; off; off >>= 1) s += __shfl_xor_sync(0xffffffffu, s, off);
    const float mean = s * (1.f / 512.f);

    float q = 0.f;
    #pragma unroll
    for (int i = 0; i < 4; i++) {
        float dx = v[i].x - mean, dy = v[i].y - mean, dz = v[i].z - mean, dw = v[i].w - mean;
        q += dx * dx + dy * dy + dz * dz + dw * dw;
    }
    #pragma unroll
    for (int off = 16; off; off >>= 1) q += __shfl_xor_sync(0xffffffffu, q, off);
    if (lane == 0)
        st[row] = make_float2(mean, rsqrtf(q * (1.f / 512.f) + 1e-5f));
}

// -------------------- segmented mean+max pool (two-phase, LN fused) --------------
__global__ __launch_bounds__(128)
void pool1_kernel(const float* __restrict__ hf, const float2* __restrict__ st,
                  float* __restrict__ psum, float* __restrict__ pmax)
{
    const int b = blockIdx.x;
    const int c = blockIdx.y * 128 + threadIdx.x;
    const int lc = blockIdx.z;
    const int tokbase = b * LL + lc * 128;
    const float* p = hf + (size_t)tokbase * CC + c;
    float s = 0.f, mx = -INFINITY;
    #pragma unroll 4
    for (int l = 0; l < 128; l++) {
        float2 stv = st[tokbase + l];
        float v = (p[(size_t)l * CC] - stv.x) * stv.y;
        s += v;
        mx = fmaxf(mx, v);
    }
    const size_t idx = ((size_t)(b * 8 + lc)) * CC + c;
    psum[idx] = s;
    pmax[idx] = mx;
}
__global__ __launch_bounds__(128)
void pool2_kernel(const float* __restrict__ psum, const float* __restrict__ pmax,
                  float* __restrict__ gp)
{
    const int b = blockIdx.x;
    const int c = blockIdx.y * 128 + threadIdx.x;
    float s = 0.f, mx = -INFINITY;
    #pragma unroll
    for (int lc = 0; lc < 8; lc++) {
        const size_t idx = ((size_t)(b * 8 + lc)) * CC + c;
        s += psum[idx];
        mx = fmaxf(mx, pmax[idx]);
    }
    gp[b * (2 * CC) + c]      = s * (1.f / (float)LL);
    gp[b * (2 * CC) + CC + c] = mx;
}

// -------------------- head ------------------------------------------------------
__global__ __launch_bounds__(128)
void head_kernel(const float* __restrict__ gp, const float* __restrict__ W,
                 const float* __restrict__ bh, float* __restrict__ out)
{
    const int tid = threadIdx.x;
    const int b = tid >> 3, o = tid & 7;
    float acc = bh[o];
    const float* gr = gp + b * 1024;
    for (int k = 0; k < 1024; k++) acc += gr[k] * W[k * 8 + o];
    out[b * 8 + o] = acc;
}

// -------------------- host launch -----------------------------------------------
static void* sym_addr(const void* sym) {
    void* p = nullptr;
    cudaGetSymbolAddress(&p, sym);
    return p;
}

extern "C" void kernel_launch(void* const* d_in, const int* in_sizes, int n_in,
                              void* d_out, int out_size)
{
    const float* feats  = (const float*)d_in[0];
    // d_in[1] = batch_idx (equal segments by construction) — unused
    const float* W_in   = (const float*)d_in[2];
    const float* b_in   = (const float*)d_in[3];
    const float* ln1_s  = (const float*)d_in[4];
    const float* ln1_b  = (const float*)d_in[5];
    const float* W_qkv  = (const float*)d_in[6];
    const float* b_qkv  = (const float*)d_in[7];
    const float* W_o    = (const float*)d_in[8];
    const float* b_o    = (const float*)d_in[9];
    const float* ln2_s  = (const float*)d_in[10];
    const float* ln2_b  = (const float*)d_in[11];
    const float* W_fc1  = (const float*)d_in[12];
    const float* b_fc1  = (const float*)d_in[13];
    const float* W_fc2  = (const float*)d_in[14];
    const float* b_fc2  = (const float*)d_in[15];
    const float* W_head = (const float*)d_in[16];
    const float* b_head = (const float*)d_in[17];
    float* out = (float*)d_out;

    float*  h     = (float*)sym_addr(g_h);
    __half* ah    = (__half*)sym_addr(g_ah);
    __half* qkvh  = (__half*)sym_addr(g_qkvh);
    __half* attnh = (__half*)sym_addr(g_attnh);
    __half* ffnh  = (__half*)sym_addr(g_ffnh);
    float*  pool  = (float*)sym_addr(g_pool);
    float*  psum  = (float*)sym_addr(g_psum);
    float*  pmax  = (float*)sym_addr(g_pmax);
    float2* lnst  = (float2*)sym_addr(g_lnst);
    __half* wt    = (__half*)sym_addr(g_wth);

    cudaFuncSetAttribute(gemm_h_kernel<0, __half>, cudaFuncAttributeMaxDynamicSharedMemorySize, GEMM_SMEM);
    cudaFuncSetAttribute(gemm_h_kernel<1, __half>, cudaFuncAttributeMaxDynamicSharedMemorySize, GEMM_SMEM);
    cudaFuncSetAttribute(gemm_h_kernel<2, float>,  cudaFuncAttributeMaxDynamicSharedMemorySize, GEMM_SMEM);
    cudaFuncSetAttribute(flash_h_kernel, cudaFuncAttributeMaxDynamicSharedMemorySize, FLASH_SMEM);

    // all weight transposes in one launch
    transpose_all_kernel<<<12288, dim3(32, 8)>>>(W_qkv, W_o, W_fc1, W_fc2, wt);

    // input projection: h = feats @ W_in + b_in   [16384,16]x[16,512] (fp32)
    gemm_simt_kernel<<<dim3(CC/64, TT/128), 256>>>(feats, W_in, b_in, h, TT, CC, CLAT);

    for (int i = 0; i < NBLK; i++) {
        __half* wb = wt + (size_t)i * WT_BLK;
        ln_kernel<<<TT/8, 256>>>(h, ln1_s + i * CC, ln1_b + i * CC, ah);
        gemm_h_kernel<0, __half><<<dim3(12, 128), 256, GEMM_SMEM>>>(
            ah, wb + WT_QKV_OFF, b_qkv + i * 3 * CC, qkvh, nullptr, TT, 3 * CC, CC);
        flash_h_kernel<<<dim3(8, NHH, TB), 256, FLASH_SMEM>>>(qkvh, attnh);
        gemm_h_kernel<2, float><<<dim3(4, 128), 256, GEMM_SMEM>>>(
            attnh, wb + WT_O_OFF, b_o + i * CC, h, h, TT, CC, CC);
        ln_kernel<<<TT/8, 256>>>(h, ln2_s + i * CC, ln2_b + i * CC, ah);
        gemm_h_kernel<1, __half><<<dim3(16, 128), 256, GEMM_SMEM>>>(
            ah, wb + WT_FC1_OFF, b_fc1 + i * CFF, ffnh, nullptr, TT, CFF, CC);
        gemm_h_kernel<2, float><<<dim3(4, 128), 256, GEMM_SMEM>>>(
            ffnh, wb + WT_FC2_OFF, b_fc2 + i * CC, h, h, TT, CC, CFF);
    }

    ln_stats_kernel<<<TT/8, 256>>>(h, lnst);
    pool1_kernel<<<dim3(TB, CC / 128, 8), 128>>>(h, lnst, psum, pmax);
    pool2_kernel<<<dim3(TB, CC / 128), 128>>>(psum, pmax, pool);
    head_kernel<<<1, 128>>>(pool, W_head, b_head, out);
    (void)in_sizes; (void)n_in; (void)out_size;
}